// round 10
// baseline (speedup 1.0000x reference)
#include <cuda_runtime.h>
#include <cuda_fp16.h>
#include <cstdint>

// ---------------------------------------------------------------------------
// WaveletAttention: 3-level MODWT (db4 dilated circular convs) -> MHA
// B=4, L=2048, D=512, H=8, dh=64
// Round 10: hybrid attention — MMA CTAs (fp16 3x, tensor pipe) + SIMT CTAs
//           (fp32 FFMA pipe) in one kernel, disjoint q-rows, 7:5 interleave.
// ---------------------------------------------------------------------------

#define Bn  4
#define Ln  2048
#define Dn  512
#define Hn  8
#define NBD (Bn * Ln * Dn)   // 4,194,304

__device__ float  g_v0[NBD];    // scratch; later holds K f32
__device__ float  g_v1[NBD];
__device__ float  g_v2[NBD];
__device__ float  g_q [NBD];
__device__ float  g_vv[NBD];    // V f32 [B][L][D]
__device__ __half g_kh [NBD];   // K hi, [B][L][D]
__device__ __half g_kl [NBD];   // K lo
__device__ __half g_vth[NBD];   // V^T hi, [B*H][64][L]
__device__ __half g_vtl[NBD];   // V^T lo

// ---------------------------------------------------------------------------
__device__ __forceinline__ void split_h2(float x, float y,
                                         unsigned& hi, unsigned& lo) {
    __half hx = __float2half_rn(x);
    __half hy = __float2half_rn(y);
    __half lx = __float2half_rn(x - __half2float(hx));
    __half ly = __float2half_rn(y - __half2float(hy));
    hi = ((unsigned)__half_as_ushort(hy) << 16) | __half_as_ushort(hx);
    lo = ((unsigned)__half_as_ushort(ly) << 16) | __half_as_ushort(lx);
}

__device__ __forceinline__ void mma_f16(float* c, const unsigned* a,
                                        unsigned b0, unsigned b1) {
    asm("mma.sync.aligned.m16n8k16.row.col.f32.f16.f16.f32 "
        "{%0,%1,%2,%3}, {%4,%5,%6,%7}, {%8,%9}, {%0,%1,%2,%3};"
        : "+f"(c[0]), "+f"(c[1]), "+f"(c[2]), "+f"(c[3])
        : "r"(a[0]), "r"(a[1]), "r"(a[2]), "r"(a[3]), "r"(b0), "r"(b1));
}

__device__ __forceinline__ uint32_t s2u(const void* p) {
    uint32_t a;
    asm("{ .reg .u64 t; cvta.to.shared.u64 t, %1; cvt.u32.u64 %0, t; }"
        : "=r"(a) : "l"(p));
    return a;
}

#define CP_ASYNC16(daddr, src)                                                 \
    asm volatile("cp.async.cg.shared.global [%0], [%1], 16;"                   \
                 :: "r"(daddr), "l"(src))
#define CP_COMMIT()  asm volatile("cp.async.commit_group;" ::: "memory")
#define CP_WAIT0()   asm volatile("cp.async.wait_group 0;" ::: "memory")

// ---------------------------------------------------------------------------
// 8-tap circular dilated convs (validated rounds 1-8)
// ---------------------------------------------------------------------------
__global__ __launch_bounds__(256) void conv1_kernel(
    const float* __restrict__ in, float* __restrict__ out,
    const float* __restrict__ frow, int dil)
{
    int idx4 = blockIdx.x * 256 + threadIdx.x;
    int d4 = idx4 & 127;
    int t  = (idx4 >> 7) & (Ln - 1);
    int b  = idx4 >> 18;
    const float* inb = in + ((long)b << 20) + (d4 << 2);
    float4 acc = {0.f, 0.f, 0.f, 0.f};
#pragma unroll
    for (int k = 0; k < 8; k++) {
        float tap = __ldg(&frow[(Ln - dil * k) & (Ln - 1)]);
        int src = (t - dil * k) & (Ln - 1);
        float4 v = *(const float4*)(inb + (src << 9));
        acc.x += tap * v.x; acc.y += tap * v.y;
        acc.z += tap * v.z; acc.w += tap * v.w;
    }
    *(float4*)(out + ((long)idx4 << 2)) = acc;
}

__global__ __launch_bounds__(256) void conv2_kernel(
    const float* __restrict__ in,
    float* __restrict__ outA, const float* __restrict__ frowA, int dilA,
    float* __restrict__ outB, const float* __restrict__ frowB, int dilB)
{
    int idx4 = blockIdx.x * 256 + threadIdx.x;
    int d4 = idx4 & 127;
    int t  = (idx4 >> 7) & (Ln - 1);
    int b  = idx4 >> 18;
    const float* inb = in + ((long)b << 20) + (d4 << 2);
    float4 aA = {0.f, 0.f, 0.f, 0.f};
    float4 aB = {0.f, 0.f, 0.f, 0.f};
#pragma unroll
    for (int k = 0; k < 8; k++) {
        float tap = __ldg(&frowA[(Ln - dilA * k) & (Ln - 1)]);
        int src = (t - dilA * k) & (Ln - 1);
        float4 v = *(const float4*)(inb + (src << 9));
        aA.x += tap * v.x; aA.y += tap * v.y;
        aA.z += tap * v.z; aA.w += tap * v.w;
    }
#pragma unroll
    for (int k = 0; k < 8; k++) {
        float tap = __ldg(&frowB[(Ln - dilB * k) & (Ln - 1)]);
        int src = (t - dilB * k) & (Ln - 1);
        float4 v = *(const float4*)(inb + (src << 9));
        aB.x += tap * v.x; aB.y += tap * v.y;
        aB.z += tap * v.z; aB.w += tap * v.w;
    }
    *(float4*)(outA + ((long)idx4 << 2)) = aA;
    *(float4*)(outB + ((long)idx4 << 2)) = aB;
}

// fused: A-output as f32 + fp16 hi/lo split, B-output f32 (for K)
__global__ __launch_bounds__(256) void conv2s_kernel(
    const float* __restrict__ in,
    __half* __restrict__ outAh, __half* __restrict__ outAl,
    float* __restrict__ outAf,
    const float* __restrict__ frowA, int dilA,
    float* __restrict__ outB, const float* __restrict__ frowB, int dilB)
{
    int idx4 = blockIdx.x * 256 + threadIdx.x;
    int d4 = idx4 & 127;
    int t  = (idx4 >> 7) & (Ln - 1);
    int b  = idx4 >> 18;
    const float* inb = in + ((long)b << 20) + (d4 << 2);
    float4 aA = {0.f, 0.f, 0.f, 0.f};
    float4 aB = {0.f, 0.f, 0.f, 0.f};
#pragma unroll
    for (int k = 0; k < 8; k++) {
        float tap = __ldg(&frowA[(Ln - dilA * k) & (Ln - 1)]);
        int src = (t - dilA * k) & (Ln - 1);
        float4 v = *(const float4*)(inb + (src << 9));
        aA.x += tap * v.x; aA.y += tap * v.y;
        aA.z += tap * v.z; aA.w += tap * v.w;
    }
#pragma unroll
    for (int k = 0; k < 8; k++) {
        float tap = __ldg(&frowB[(Ln - dilB * k) & (Ln - 1)]);
        int src = (t - dilB * k) & (Ln - 1);
        float4 v = *(const float4*)(inb + (src << 9));
        aB.x += tap * v.x; aB.y += tap * v.y;
        aB.z += tap * v.z; aB.w += tap * v.w;
    }
    unsigned h01, l01, h23, l23;
    split_h2(aA.x, aA.y, h01, l01);
    split_h2(aA.z, aA.w, h23, l23);
    *(uint2*)(outAh + ((long)idx4 << 2)) = make_uint2(h01, h23);
    *(uint2*)(outAl + ((long)idx4 << 2)) = make_uint2(l01, l23);
    *(float4*)(outAf + ((long)idx4 << 2)) = aA;
    *(float4*)(outB + ((long)idx4 << 2)) = aB;
}

__global__ __launch_bounds__(256) void vtrans_kernel(
    const float* __restrict__ v,
    __half* __restrict__ vth, __half* __restrict__ vtl)
{
    __shared__ float tile[64][65];
    int t0 = blockIdx.x * 64;
    int bh = blockIdx.y;
    int b = bh >> 3, h = bh & 7;
    const float* src = v + ((long)b * Ln + t0) * Dn + h * 64;
#pragma unroll
    for (int it = 0; it < 16; it++) {
        int o = it * 256 + threadIdx.x;
        int r = o >> 6, c = o & 63;
        tile[r][c] = src[(long)r * Dn + c];
    }
    __syncthreads();
    __half* dh_ = vth + (long)bh * 64 * Ln + t0;
    __half* dl_ = vtl + (long)bh * 64 * Ln + t0;
#pragma unroll
    for (int it = 0; it < 16; it++) {
        int o = it * 256 + threadIdx.x;
        int key = o & 63, dh = o >> 6;
        float x = tile[key][dh];
        __half hi = __float2half_rn(x);
        __half lo = __float2half_rn(x - __half2float(hi));
        dh_[(long)dh * Ln + key] = hi;
        dl_[(long)dh * Ln + key] = lo;
    }
}

// ---------------------------------------------------------------------------
// Hybrid attention kernel.
// grid 647 blocks, 256 threads, 110592 B dynamic smem (2 CTA/SM).
// Unit = (bh, 64-row q-tile): 1024 units total.
//   MMA CTAs: 377 items, units [0, 754)   (128 rows each, tensor pipe)
//   SIMT CTAs: 270 items, units [754,1024) (64 rows each, fma pipe)
// Interleave: per 12 consecutive bids, 5 SIMT + 7 MMA.
// ---------------------------------------------------------------------------
#define STRW 36                    // words per smem row (72 halfs)
#define TILEW (64 * STRW)
#define BUFW  (4 * TILEW)
#define PHOFF (2 * BUFW)
#define PLOFF (PHOFF + 128 * STRW)
#define ASMEM ((2 * BUFW + 2 * 128 * STRW) * 4)   // 110592

__global__ __launch_bounds__(256, 2) void attn_hybrid(
    const float* __restrict__ Qg,
    const __half* __restrict__ Khg, const __half* __restrict__ Klg,
    const __half* __restrict__ Vhg, const __half* __restrict__ Vlg,
    const float* __restrict__ Kfg, const float* __restrict__ Vfg,
    float* __restrict__ O)
{
    extern __shared__ char smc[];
    const int tid = threadIdx.x;
    const int bidx = blockIdx.x;
    const int grp = bidx / 12, rr = bidx - grp * 12;

    if (rr >= 5) {
        // ================= MMA path (round-8 code) =========================
        const int item = grp * 7 + (rr - 5);          // 0..376
        const int u = 2 * item;
        const int bh = u >> 5;
        const int b = bh >> 3, h = bh & 7;
        const int q0 = (u & 31) * 64;

        unsigned* sm_u = (unsigned*)smc;
        const uint32_t sb = s2u(smc);
        const int lane = tid & 31, warp = tid >> 5;
        const int g = lane >> 2, tg = lane & 3;

        unsigned qah[4][4], qal[4][4];
        {
            const float* Qp = Qg + ((long)b * Ln + q0 + warp * 16) * Dn + h * 64;
#pragma unroll
            for (int kt = 0; kt < 4; kt++)
#pragma unroll
                for (int part = 0; part < 4; part++) {
                    int row = g + (part & 1) * 8;
                    int col = kt * 16 + ((part >> 1) << 3) + 2 * tg;
                    float2 x = *(const float2*)(Qp + row * Dn + col);
                    split_h2(x.x * 0.125f, x.y * 0.125f,
                             qah[kt][part], qal[kt][part]);
                }
        }

        const __half* Kb  = Khg + (long)b * Ln * Dn + h * 64;
        const __half* Klb = Klg + (long)b * Ln * Dn + h * 64;
        const __half* Vb  = Vhg + (long)bh * 64 * Ln;
        const __half* Vlb = Vlg + (long)bh * 64 * Ln;

        auto issue_copy = [&](int tile, int bufsel) {
            const int k0 = tile * 64;
            const uint32_t bufbase = sb + (uint32_t)(bufsel * BUFW) * 4u;
#pragma unroll
            for (int j = 0; j < 8; j++) {
                int flat = j * 256 + tid;
                int arr = flat >> 9, rem = flat & 511;
                int row = rem >> 3, c = rem & 7;
                const __half* src;
                uint32_t doff;
                if (arr == 0)      { src = Kb  + (long)(k0 + row) * Dn + c * 8; doff = 0; }
                else if (arr == 1) { src = Klb + (long)(k0 + row) * Dn + c * 8; doff = TILEW; }
                else if (arr == 2) { src = Vb  + (long)row * Ln + k0 + c * 8;   doff = 2 * TILEW; }
                else               { src = Vlb + (long)row * Ln + k0 + c * 8;   doff = 3 * TILEW; }
                uint32_t daddr = bufbase + (doff + row * STRW + c * 4) * 4u;
                CP_ASYNC16(daddr, src);
            }
            CP_COMMIT();
        };

        float m_[2] = {-1e30f, -1e30f}, l_[2] = {0.f, 0.f};
        float oacc[8][4];
#pragma unroll
        for (int nt = 0; nt < 8; nt++)
#pragma unroll
            for (int j = 0; j < 4; j++) oacc[nt][j] = 0.f;

        unsigned* p0h = sm_u + PHOFF + (warp * 16 + g) * STRW;
        unsigned* p1h = p0h + 8 * STRW;
        unsigned* p0l = sm_u + PLOFF + (warp * 16 + g) * STRW;
        unsigned* p1l = p0l + 8 * STRW;

        issue_copy(0, 0);

        for (int it = 0; it < 32; it++) {
            CP_WAIT0();
            __syncthreads();
            if (it < 31) issue_copy(it + 1, (it + 1) & 1);

            unsigned* buf = sm_u + (it & 1) * BUFW;
            unsigned* sKh = buf;
            unsigned* sKl = buf + TILEW;
            unsigned* sVh = buf + 2 * TILEW;
            unsigned* sVl = buf + 3 * TILEW;

            float sc[8][4];
#pragma unroll
            for (int nt = 0; nt < 8; nt++)
                sc[nt][0] = sc[nt][1] = sc[nt][2] = sc[nt][3] = 0.f;
#pragma unroll
            for (int kt = 0; kt < 4; kt++)
#pragma unroll
                for (int nt = 0; nt < 8; nt++) {
                    const unsigned* krh = sKh + (nt * 8 + g) * STRW + kt * 8;
                    const unsigned* krl = sKl + (nt * 8 + g) * STRW + kt * 8;
                    unsigned b0h = krh[tg], b1h = krh[tg + 4];
                    unsigned b0l = krl[tg], b1l = krl[tg + 4];
                    mma_f16(sc[nt], qal[kt], b0h, b1h);
                    mma_f16(sc[nt], qah[kt], b0l, b1l);
                    mma_f16(sc[nt], qah[kt], b0h, b1h);
                }

            float rmax[2] = {-1e30f, -1e30f};
#pragma unroll
            for (int nt = 0; nt < 8; nt++) {
                rmax[0] = fmaxf(rmax[0], fmaxf(sc[nt][0], sc[nt][1]));
                rmax[1] = fmaxf(rmax[1], fmaxf(sc[nt][2], sc[nt][3]));
            }
#pragma unroll
            for (int o = 1; o <= 2; o <<= 1) {
                rmax[0] = fmaxf(rmax[0], __shfl_xor_sync(0xffffffffu, rmax[0], o));
                rmax[1] = fmaxf(rmax[1], __shfl_xor_sync(0xffffffffu, rmax[1], o));
            }
            float corr[2];
#pragma unroll
            for (int r2 = 0; r2 < 2; r2++) {
                float mn = fmaxf(m_[r2], rmax[r2]);
                corr[r2] = __expf(m_[r2] - mn);
                m_[r2] = mn;
            }
            float rsum[2] = {0.f, 0.f};
#pragma unroll
            for (int nt = 0; nt < 8; nt++) {
                float p0 = __expf(sc[nt][0] - m_[0]);
                float p1 = __expf(sc[nt][1] - m_[0]);
                float p2 = __expf(sc[nt][2] - m_[1]);
                float p3 = __expf(sc[nt][3] - m_[1]);
                rsum[0] += p0 + p1; rsum[1] += p2 + p3;
                unsigned h01, l01, h23, l23;
                split_h2(p0, p1, h01, l01);
                split_h2(p2, p3, h23, l23);
                p0h[nt * 4 + tg] = h01; p0l[nt * 4 + tg] = l01;
                p1h[nt * 4 + tg] = h23; p1l[nt * 4 + tg] = l23;
            }
#pragma unroll
            for (int o = 1; o <= 2; o <<= 1) {
                rsum[0] += __shfl_xor_sync(0xffffffffu, rsum[0], o);
                rsum[1] += __shfl_xor_sync(0xffffffffu, rsum[1], o);
            }
            l_[0] = l_[0] * corr[0] + rsum[0];
            l_[1] = l_[1] * corr[1] + rsum[1];
#pragma unroll
            for (int nt = 0; nt < 8; nt++) {
                oacc[nt][0] *= corr[0]; oacc[nt][1] *= corr[0];
                oacc[nt][2] *= corr[1]; oacc[nt][3] *= corr[1];
            }
            __syncwarp();

#pragma unroll
            for (int kt = 0; kt < 4; kt++) {
                unsigned pah[4], pal[4];
                pah[0] = p0h[kt * 8 + tg];     pal[0] = p0l[kt * 8 + tg];
                pah[1] = p1h[kt * 8 + tg];     pal[1] = p1l[kt * 8 + tg];
                pah[2] = p0h[kt * 8 + tg + 4]; pal[2] = p0l[kt * 8 + tg + 4];
                pah[3] = p1h[kt * 8 + tg + 4]; pal[3] = p1l[kt * 8 + tg + 4];
#pragma unroll
                for (int nt = 0; nt < 8; nt++) {
                    const unsigned* vrh = sVh + (nt * 8 + g) * STRW + kt * 8;
                    const unsigned* vrl = sVl + (nt * 8 + g) * STRW + kt * 8;
                    unsigned b0h = vrh[tg], b1h = vrh[tg + 4];
                    unsigned b0l = vrl[tg], b1l = vrl[tg + 4];
                    mma_f16(oacc[nt], pal, b0h, b1h);
                    mma_f16(oacc[nt], pah, b0l, b1l);
                    mma_f16(oacc[nt], pah, b0h, b1h);
                }
            }
        }

        float inv0 = 1.f / l_[0], inv1 = 1.f / l_[1];
        long row0 = (long)b * Ln + q0 + warp * 16 + g;
        long row1 = row0 + 8;
#pragma unroll
        for (int nt = 0; nt < 8; nt++) {
            int col = h * 64 + nt * 8 + 2 * tg;
            float2 v0 = {oacc[nt][0] * inv0, oacc[nt][1] * inv0};
            float2 v1 = {oacc[nt][2] * inv1, oacc[nt][3] * inv1};
            *(float2*)(O + row0 * Dn + col) = v0;
            *(float2*)(O + row1 * Dn + col) = v1;
        }
    } else {
        // ================= SIMT fp32 path (round-1 code) ===================
        const int item = grp * 5 + rr;                // 0..269
        const int u = 754 + item;
        const int bh = u >> 5;
        const int b = bh >> 3, h = bh & 7;
        const int q0 = (u & 31) * 64;

        float* smf = (float*)smc;
        float* Qs = smf;                 // [64][64]
        float* Ks = Qs + 64 * 64;        // [64][65]
        float* Vs = Ks + 64 * 65;        // [64][64]
        float* Ps = Vs + 64 * 64;        // [64][68]

        const int tx = tid & 15, ty = tid >> 4;
        const float* Qp = Qg + ((long)b * Ln + q0) * Dn + h * 64;
        const float* Kp = Kfg + (long)b * Ln * Dn + h * 64;
        const float* Vp = Vfg + (long)b * Ln * Dn + h * 64;
        const float scale = 0.125f;

#pragma unroll
        for (int i = 0; i < 4; i++) {
            int e4 = tid + i * 256;
            int r = e4 >> 4, c4 = e4 & 15;
            float4 v = *(const float4*)(Qp + (long)r * Dn + c4 * 4);
            v.x *= scale; v.y *= scale; v.z *= scale; v.w *= scale;
            *(float4*)(Qs + r * 64 + c4 * 4) = v;
        }

        float m[4], l[4], acc[4][4];
#pragma unroll
        for (int i = 0; i < 4; i++) {
            m[i] = -1e30f; l[i] = 0.f;
#pragma unroll
            for (int j = 0; j < 4; j++) acc[i][j] = 0.f;
        }
        __syncthreads();

        for (int k0 = 0; k0 < Ln; k0 += 64) {
#pragma unroll
            for (int i = 0; i < 4; i++) {
                int e4 = tid + i * 256;
                int r = e4 >> 4, c4 = e4 & 15;
                float4 kv = *(const float4*)(Kp + (long)(k0 + r) * Dn + c4 * 4);
                float* kd = Ks + r * 65 + c4 * 4;
                kd[0] = kv.x; kd[1] = kv.y; kd[2] = kv.z; kd[3] = kv.w;
                float4 vv = *(const float4*)(Vp + (long)(k0 + r) * Dn + c4 * 4);
                *(float4*)(Vs + r * 64 + c4 * 4) = vv;
            }
            __syncthreads();

            float s[4][4];
#pragma unroll
            for (int i = 0; i < 4; i++)
#pragma unroll
                for (int j = 0; j < 4; j++) s[i][j] = 0.f;

#pragma unroll 16
            for (int kk = 0; kk < 64; kk++) {
                float qv[4], kv[4];
#pragma unroll
                for (int i = 0; i < 4; i++) qv[i] = Qs[(ty * 4 + i) * 64 + kk];
#pragma unroll
                for (int j = 0; j < 4; j++) kv[j] = Ks[(tx + 16 * j) * 65 + kk];
#pragma unroll
                for (int i = 0; i < 4; i++)
#pragma unroll
                    for (int j = 0; j < 4; j++) s[i][j] += qv[i] * kv[j];
            }

#pragma unroll
            for (int i = 0; i < 4; i++) {
                float mx = fmaxf(fmaxf(s[i][0], s[i][1]), fmaxf(s[i][2], s[i][3]));
#pragma unroll
                for (int o = 8; o; o >>= 1)
                    mx = fmaxf(mx, __shfl_xor_sync(0xffffffffu, mx, o, 16));
                float mn = fmaxf(m[i], mx);
                float corr = __expf(m[i] - mn);
                m[i] = mn;
                float ls = 0.f;
#pragma unroll
                for (int j = 0; j < 4; j++) {
                    float p = __expf(s[i][j] - mn);
                    s[i][j] = p;
                    ls += p;
                }
#pragma unroll
                for (int o = 8; o; o >>= 1)
                    ls += __shfl_xor_sync(0xffffffffu, ls, o, 16);
                l[i] = l[i] * corr + ls;
#pragma unroll
                for (int j = 0; j < 4; j++) {
                    acc[i][j] *= corr;
                    Ps[(ty * 4 + i) * 68 + tx + 16 * j] = s[i][j];
                }
            }
            __syncwarp();

#pragma unroll 16
            for (int kk = 0; kk < 64; kk++) {
                float pv[4], vv[4];
#pragma unroll
                for (int i = 0; i < 4; i++) pv[i] = Ps[(ty * 4 + i) * 68 + kk];
#pragma unroll
                for (int j = 0; j < 4; j++) vv[j] = Vs[kk * 64 + tx + 16 * j];
#pragma unroll
                for (int i = 0; i < 4; i++)
#pragma unroll
                    for (int j = 0; j < 4; j++) acc[i][j] += pv[i] * vv[j];
            }
            __syncthreads();
        }

#pragma unroll
        for (int i = 0; i < 4; i++) {
            float inv = 1.f / l[i];
            long row = (long)b * Ln + q0 + ty * 4 + i;
#pragma unroll
            for (int j = 0; j < 4; j++)
                O[row * Dn + h * 64 + tx + 16 * j] = acc[i][j] * inv;
        }
    }
}

// ---------------------------------------------------------------------------
extern "C" void kernel_launch(void* const* d_in, const int* in_sizes, int n_in,
                              void* d_out, int out_size)
{
    const float* x  = (const float*)d_in[0];
    const float* vf = (const float*)d_in[1];
    const float* wf = (const float*)d_in[2];
    float* out = (float*)d_out;

    float *v0, *v1, *v2, *q, *vv;
    __half *kh, *kl, *vth, *vtl;
    cudaGetSymbolAddress((void**)&v0,  g_v0);
    cudaGetSymbolAddress((void**)&v1,  g_v1);
    cudaGetSymbolAddress((void**)&v2,  g_v2);
    cudaGetSymbolAddress((void**)&q,   g_q);
    cudaGetSymbolAddress((void**)&vv,  g_vv);
    cudaGetSymbolAddress((void**)&kh,  g_kh);
    cudaGetSymbolAddress((void**)&kl,  g_kl);
    cudaGetSymbolAddress((void**)&vth, g_vth);
    cudaGetSymbolAddress((void**)&vtl, g_vtl);

    const size_t LL = (size_t)Ln * Ln;
    const int cblocks = (NBD / 4) / 256;

    // v0 = L0(x); {q = H0(v0), v1 = L1(v0)};
    // {K = H1(v1) -> kh/kl + f32 into v0 (free), v2 = L2(v1)}; vv = H2(v2)
    conv1_kernel<<<cblocks, 256>>>(x, v0, vf, 1);
    conv2_kernel<<<cblocks, 256>>>(v0, q, wf, 1, v1, vf + LL, 2);
    conv2s_kernel<<<cblocks, 256>>>(v1, kh, kl, v0, wf + LL, 2, v2, vf + 2 * LL, 4);
    conv1_kernel<<<cblocks, 256>>>(v2, vv, wf + 2 * LL, 4);
    vtrans_kernel<<<dim3(Ln / 64, Bn * Hn), 256>>>(vv, vth, vtl);

    cudaFuncSetAttribute(attn_hybrid,
                         cudaFuncAttributeMaxDynamicSharedMemorySize, ASMEM);
    attn_hybrid<<<647, 256, ASMEM>>>(q, kh, kl, vth, vtl, v0, vv, out);
}

// round 11
// speedup vs baseline: 1.7094x; 1.7094x over previous
#include <cuda_runtime.h>
#include <cuda_fp16.h>
#include <cstdint>

// ---------------------------------------------------------------------------
// WaveletAttention: 3-level MODWT (db4 dilated circular convs) -> MHA
// B=4, L=2048, D=512, H=8, dh=64
// Round 11: scaled-residual 2-MMA fp16 split (lambda=32) on both GEMMs
//           S = (1-1/l)*Ah*Bh + (1/l)*X*Y,  X = fl16(Ah + l*(A-Ah))
// ---------------------------------------------------------------------------

#define Bn  4
#define Ln  2048
#define Dn  512
#define Hn  8
#define NBD (Bn * Ln * Dn)   // 4,194,304

#define LAM 32.0f
#define C1  0.96875f    // 1 - 1/32
#define C2  0.03125f    // 1/32

__device__ float  g_v0[NBD];
__device__ float  g_v1[NBD];
__device__ float  g_v2[NBD];
__device__ float  g_q [NBD];
__device__ float  g_vv[NBD];
__device__ __half g_kh [NBD];   // K hi, [B][L][D]
__device__ __half g_kx [NBD];   // K X-form
__device__ __half g_vth[NBD];   // V^T hi, [B*H][64][L]
__device__ __half g_vtx[NBD];   // V^T X-form

// ---------------------------------------------------------------------------
// split: hi = fl16(v), xx = fl16(hi + 32*(v - hi)); packed pairs
__device__ __forceinline__ void split_x2(float x, float y,
                                         unsigned& hi, unsigned& xx) {
    __half hx = __float2half_rn(x);
    __half hy = __float2half_rn(y);
    float fx = __half2float(hx), fy = __half2float(hy);
    __half xxh = __float2half_rn(fx + LAM * (x - fx));
    __half xyh = __float2half_rn(fy + LAM * (y - fy));
    hi = ((unsigned)__half_as_ushort(hy) << 16) | __half_as_ushort(hx);
    xx = ((unsigned)__half_as_ushort(xyh) << 16) | __half_as_ushort(xxh);
}

__device__ __forceinline__ void mma_f16(float* c, const unsigned* a,
                                        unsigned b0, unsigned b1) {
    asm("mma.sync.aligned.m16n8k16.row.col.f32.f16.f16.f32 "
        "{%0,%1,%2,%3}, {%4,%5,%6,%7}, {%8,%9}, {%0,%1,%2,%3};"
        : "+f"(c[0]), "+f"(c[1]), "+f"(c[2]), "+f"(c[3])
        : "r"(a[0]), "r"(a[1]), "r"(a[2]), "r"(a[3]), "r"(b0), "r"(b1));
}

__device__ __forceinline__ uint32_t s2u(const void* p) {
    uint32_t a;
    asm("{ .reg .u64 t; cvta.to.shared.u64 t, %1; cvt.u32.u64 %0, t; }"
        : "=r"(a) : "l"(p));
    return a;
}

#define CP_ASYNC16(daddr, src)                                                 \
    asm volatile("cp.async.cg.shared.global [%0], [%1], 16;"                   \
                 :: "r"(daddr), "l"(src))
#define CP_COMMIT()  asm volatile("cp.async.commit_group;" ::: "memory")
#define CP_WAIT0()   asm volatile("cp.async.wait_group 0;" ::: "memory")

// ---------------------------------------------------------------------------
// 8-tap circular dilated convs (validated rounds 1-8)
// ---------------------------------------------------------------------------
__global__ __launch_bounds__(256) void conv1_kernel(
    const float* __restrict__ in, float* __restrict__ out,
    const float* __restrict__ frow, int dil)
{
    int idx4 = blockIdx.x * 256 + threadIdx.x;
    int d4 = idx4 & 127;
    int t  = (idx4 >> 7) & (Ln - 1);
    int b  = idx4 >> 18;
    const float* inb = in + ((long)b << 20) + (d4 << 2);
    float4 acc = {0.f, 0.f, 0.f, 0.f};
#pragma unroll
    for (int k = 0; k < 8; k++) {
        float tap = __ldg(&frow[(Ln - dil * k) & (Ln - 1)]);
        int src = (t - dil * k) & (Ln - 1);
        float4 v = *(const float4*)(inb + (src << 9));
        acc.x += tap * v.x; acc.y += tap * v.y;
        acc.z += tap * v.z; acc.w += tap * v.w;
    }
    *(float4*)(out + ((long)idx4 << 2)) = acc;
}

__global__ __launch_bounds__(256) void conv2_kernel(
    const float* __restrict__ in,
    float* __restrict__ outA, const float* __restrict__ frowA, int dilA,
    float* __restrict__ outB, const float* __restrict__ frowB, int dilB)
{
    int idx4 = blockIdx.x * 256 + threadIdx.x;
    int d4 = idx4 & 127;
    int t  = (idx4 >> 7) & (Ln - 1);
    int b  = idx4 >> 18;
    const float* inb = in + ((long)b << 20) + (d4 << 2);
    float4 aA = {0.f, 0.f, 0.f, 0.f};
    float4 aB = {0.f, 0.f, 0.f, 0.f};
#pragma unroll
    for (int k = 0; k < 8; k++) {
        float tap = __ldg(&frowA[(Ln - dilA * k) & (Ln - 1)]);
        int src = (t - dilA * k) & (Ln - 1);
        float4 v = *(const float4*)(inb + (src << 9));
        aA.x += tap * v.x; aA.y += tap * v.y;
        aA.z += tap * v.z; aA.w += tap * v.w;
    }
#pragma unroll
    for (int k = 0; k < 8; k++) {
        float tap = __ldg(&frowB[(Ln - dilB * k) & (Ln - 1)]);
        int src = (t - dilB * k) & (Ln - 1);
        float4 v = *(const float4*)(inb + (src << 9));
        aB.x += tap * v.x; aB.y += tap * v.y;
        aB.z += tap * v.z; aB.w += tap * v.w;
    }
    *(float4*)(outA + ((long)idx4 << 2)) = aA;
    *(float4*)(outB + ((long)idx4 << 2)) = aB;
}

// fused: A-output as fp16 hi/X split, B-output f32 (for K)
__global__ __launch_bounds__(256) void conv2s_kernel(
    const float* __restrict__ in,
    __half* __restrict__ outAh, __half* __restrict__ outAx,
    const float* __restrict__ frowA, int dilA,
    float* __restrict__ outB, const float* __restrict__ frowB, int dilB)
{
    int idx4 = blockIdx.x * 256 + threadIdx.x;
    int d4 = idx4 & 127;
    int t  = (idx4 >> 7) & (Ln - 1);
    int b  = idx4 >> 18;
    const float* inb = in + ((long)b << 20) + (d4 << 2);
    float4 aA = {0.f, 0.f, 0.f, 0.f};
    float4 aB = {0.f, 0.f, 0.f, 0.f};
#pragma unroll
    for (int k = 0; k < 8; k++) {
        float tap = __ldg(&frowA[(Ln - dilA * k) & (Ln - 1)]);
        int src = (t - dilA * k) & (Ln - 1);
        float4 v = *(const float4*)(inb + (src << 9));
        aA.x += tap * v.x; aA.y += tap * v.y;
        aA.z += tap * v.z; aA.w += tap * v.w;
    }
#pragma unroll
    for (int k = 0; k < 8; k++) {
        float tap = __ldg(&frowB[(Ln - dilB * k) & (Ln - 1)]);
        int src = (t - dilB * k) & (Ln - 1);
        float4 v = *(const float4*)(inb + (src << 9));
        aB.x += tap * v.x; aB.y += tap * v.y;
        aB.z += tap * v.z; aB.w += tap * v.w;
    }
    unsigned h01, x01, h23, x23;
    split_x2(aA.x, aA.y, h01, x01);
    split_x2(aA.z, aA.w, h23, x23);
    *(uint2*)(outAh + ((long)idx4 << 2)) = make_uint2(h01, h23);
    *(uint2*)(outAx + ((long)idx4 << 2)) = make_uint2(x01, x23);
    *(float4*)(outB + ((long)idx4 << 2)) = aB;
}

__global__ __launch_bounds__(256) void vtrans_kernel(
    const float* __restrict__ v,
    __half* __restrict__ vth, __half* __restrict__ vtx)
{
    __shared__ float tile[64][65];
    int t0 = blockIdx.x * 64;
    int bh = blockIdx.y;
    int b = bh >> 3, h = bh & 7;
    const float* src = v + ((long)b * Ln + t0) * Dn + h * 64;
#pragma unroll
    for (int it = 0; it < 16; it++) {
        int o = it * 256 + threadIdx.x;
        int r = o >> 6, c = o & 63;
        tile[r][c] = src[(long)r * Dn + c];
    }
    __syncthreads();
    __half* dh_ = vth + (long)bh * 64 * Ln + t0;
    __half* dx_ = vtx + (long)bh * 64 * Ln + t0;
#pragma unroll
    for (int it = 0; it < 16; it++) {
        int o = it * 256 + threadIdx.x;
        int key = o & 63, dh = o >> 6;
        float x = tile[key][dh];
        __half hi = __float2half_rn(x);
        float fh = __half2float(hi);
        __half xx = __float2half_rn(fh + LAM * (x - fh));
        dh_[(long)dh * Ln + key] = hi;
        dx_[(long)dh * Ln + key] = xx;
    }
}

// ---------------------------------------------------------------------------
// 2-MMA scaled-residual flash attention, cp.async double-buffered K/V.
// Grid (L/128, B*H), 256 threads = 8 warps; warp owns 16 q-rows; BK=64.
// smem words: 2 bufs x [Kh|Kx|Vh|Vx][64][36w] + Ph[128][36w] + Px[128][36w]
// ---------------------------------------------------------------------------
#define STRW 36
#define TILEW (64 * STRW)
#define BUFW  (4 * TILEW)
#define PHOFF (2 * BUFW)
#define PXOFF (PHOFF + 128 * STRW)
#define ASMEM ((2 * BUFW + 2 * 128 * STRW) * 4)   // 110592

__global__ __launch_bounds__(256, 2) void attn_kernel(
    const float* __restrict__ Qg,
    const __half* __restrict__ Khg, const __half* __restrict__ Kxg,
    const __half* __restrict__ Vhg, const __half* __restrict__ Vxg,
    float* __restrict__ O)
{
    extern __shared__ unsigned sm_u[];
    const uint32_t sb = s2u(sm_u);

    const int tid = threadIdx.x;
    const int lane = tid & 31, warp = tid >> 5;
    const int g = lane >> 2, tg = lane & 3;
    const int bh = blockIdx.y;
    const int b = bh >> 3, h = bh & 7;
    const int q0 = blockIdx.x * 128;

    // ---- Q fragments (scaled, hi/X split)
    unsigned qah[4][4], qax[4][4];
    {
        const float* Qp = Qg + ((long)b * Ln + q0 + warp * 16) * Dn + h * 64;
#pragma unroll
        for (int kt = 0; kt < 4; kt++)
#pragma unroll
            for (int part = 0; part < 4; part++) {
                int row = g + (part & 1) * 8;
                int col = kt * 16 + ((part >> 1) << 3) + 2 * tg;
                float2 x = *(const float2*)(Qp + row * Dn + col);
                split_x2(x.x * 0.125f, x.y * 0.125f, qah[kt][part], qax[kt][part]);
            }
    }

    const __half* Kb  = Khg + (long)b * Ln * Dn + h * 64;
    const __half* Kxb = Kxg + (long)b * Ln * Dn + h * 64;
    const __half* Vb  = Vhg + (long)bh * 64 * Ln;
    const __half* Vxb = Vxg + (long)bh * 64 * Ln;

    auto issue_copy = [&](int tile, int bufsel) {
        const int k0 = tile * 64;
        const uint32_t bufbase = sb + (uint32_t)(bufsel * BUFW) * 4u;
#pragma unroll
        for (int j = 0; j < 8; j++) {
            int flat = j * 256 + tid;
            int arr = flat >> 9, rem = flat & 511;
            int row = rem >> 3, c = rem & 7;
            const __half* src;
            uint32_t doff;
            if (arr == 0)      { src = Kb  + (long)(k0 + row) * Dn + c * 8; doff = 0; }
            else if (arr == 1) { src = Kxb + (long)(k0 + row) * Dn + c * 8; doff = TILEW; }
            else if (arr == 2) { src = Vb  + (long)row * Ln + k0 + c * 8;   doff = 2 * TILEW; }
            else               { src = Vxb + (long)row * Ln + k0 + c * 8;   doff = 3 * TILEW; }
            uint32_t daddr = bufbase + (doff + row * STRW + c * 4) * 4u;
            CP_ASYNC16(daddr, src);
        }
        CP_COMMIT();
    };

    float m_[2] = {-1e30f, -1e30f}, l_[2] = {0.f, 0.f};
    float oacc[8][4];
#pragma unroll
    for (int nt = 0; nt < 8; nt++)
#pragma unroll
        for (int j = 0; j < 4; j++) oacc[nt][j] = 0.f;

    unsigned* p0h = sm_u + PHOFF + (warp * 16 + g) * STRW;
    unsigned* p1h = p0h + 8 * STRW;
    unsigned* p0x = sm_u + PXOFF + (warp * 16 + g) * STRW;
    unsigned* p1x = p0x + 8 * STRW;

    issue_copy(0, 0);

    for (int it = 0; it < 32; it++) {
        CP_WAIT0();
        __syncthreads();
        if (it < 31) issue_copy(it + 1, (it + 1) & 1);

        unsigned* buf = sm_u + (it & 1) * BUFW;
        unsigned* sKh = buf;
        unsigned* sKx = buf + TILEW;
        unsigned* sVh = buf + 2 * TILEW;
        unsigned* sVx = buf + 3 * TILEW;

        // ---- S = Q K^T  (2-MMA scheme, dual accumulators, fp32 combine)
        float sc[8][4];
#pragma unroll
        for (int nt = 0; nt < 8; nt++) {
            float ch[4] = {0.f, 0.f, 0.f, 0.f};
            float cx[4] = {0.f, 0.f, 0.f, 0.f};
            const unsigned* krh = sKh + (nt * 8 + g) * STRW;
            const unsigned* krx = sKx + (nt * 8 + g) * STRW;
#pragma unroll
            for (int kt = 0; kt < 4; kt++) {
                mma_f16(ch, qah[kt], krh[kt * 8 + tg], krh[kt * 8 + tg + 4]);
                mma_f16(cx, qax[kt], krx[kt * 8 + tg], krx[kt * 8 + tg + 4]);
            }
#pragma unroll
            for (int j = 0; j < 4; j++) sc[nt][j] = C1 * ch[j] + C2 * cx[j];
        }

        // ---- online softmax (rows g, g+8 of this warp)
        float rmax[2] = {-1e30f, -1e30f};
#pragma unroll
        for (int nt = 0; nt < 8; nt++) {
            rmax[0] = fmaxf(rmax[0], fmaxf(sc[nt][0], sc[nt][1]));
            rmax[1] = fmaxf(rmax[1], fmaxf(sc[nt][2], sc[nt][3]));
        }
#pragma unroll
        for (int o = 1; o <= 2; o <<= 1) {
            rmax[0] = fmaxf(rmax[0], __shfl_xor_sync(0xffffffffu, rmax[0], o));
            rmax[1] = fmaxf(rmax[1], __shfl_xor_sync(0xffffffffu, rmax[1], o));
        }
        float corr[2];
#pragma unroll
        for (int r = 0; r < 2; r++) {
            float mn = fmaxf(m_[r], rmax[r]);
            corr[r] = __expf(m_[r] - mn);
            m_[r] = mn;
        }
        float rsum[2] = {0.f, 0.f};
#pragma unroll
        for (int nt = 0; nt < 8; nt++) {
            float p0 = __expf(sc[nt][0] - m_[0]);
            float p1 = __expf(sc[nt][1] - m_[0]);
            float p2 = __expf(sc[nt][2] - m_[1]);
            float p3 = __expf(sc[nt][3] - m_[1]);
            rsum[0] += p0 + p1; rsum[1] += p2 + p3;
            unsigned h01, x01, h23, x23;
            split_x2(p0, p1, h01, x01);
            split_x2(p2, p3, h23, x23);
            p0h[nt * 4 + tg] = h01; p0x[nt * 4 + tg] = x01;
            p1h[nt * 4 + tg] = h23; p1x[nt * 4 + tg] = x23;
        }
#pragma unroll
        for (int o = 1; o <= 2; o <<= 1) {
            rsum[0] += __shfl_xor_sync(0xffffffffu, rsum[0], o);
            rsum[1] += __shfl_xor_sync(0xffffffffu, rsum[1], o);
        }
        l_[0] = l_[0] * corr[0] + rsum[0];
        l_[1] = l_[1] * corr[1] + rsum[1];
#pragma unroll
        for (int nt = 0; nt < 8; nt++) {
            oacc[nt][0] *= corr[0]; oacc[nt][1] *= corr[0];
            oacc[nt][2] *= corr[1]; oacc[nt][3] *= corr[1];
        }
        __syncwarp();   // P rows are per-warp

        // ---- O += P V  (2-MMA scheme; P fragments preloaded for the tile)
        unsigned pah[4][4], pax[4][4];
#pragma unroll
        for (int kt = 0; kt < 4; kt++) {
            pah[kt][0] = p0h[kt * 8 + tg];     pax[kt][0] = p0x[kt * 8 + tg];
            pah[kt][1] = p1h[kt * 8 + tg];     pax[kt][1] = p1x[kt * 8 + tg];
            pah[kt][2] = p0h[kt * 8 + tg + 4]; pax[kt][2] = p0x[kt * 8 + tg + 4];
            pah[kt][3] = p1h[kt * 8 + tg + 4]; pax[kt][3] = p1x[kt * 8 + tg + 4];
        }
#pragma unroll
        for (int nt = 0; nt < 8; nt++) {
            float ch[4] = {0.f, 0.f, 0.f, 0.f};
            float cx[4] = {0.f, 0.f, 0.f, 0.f};
            const unsigned* vrh = sVh + (nt * 8 + g) * STRW;
            const unsigned* vrx = sVx + (nt * 8 + g) * STRW;
#pragma unroll
            for (int kt = 0; kt < 4; kt++) {
                mma_f16(ch, pah[kt], vrh[kt * 8 + tg], vrh[kt * 8 + tg + 4]);
                mma_f16(cx, pax[kt], vrx[kt * 8 + tg], vrx[kt * 8 + tg + 4]);
            }
#pragma unroll
            for (int j = 0; j < 4; j++)
                oacc[nt][j] += C1 * ch[j] + C2 * cx[j];
        }
    }

    // ---- epilogue
    float inv0 = 1.f / l_[0], inv1 = 1.f / l_[1];
    long row0 = (long)b * Ln + q0 + warp * 16 + g;
    long row1 = row0 + 8;
#pragma unroll
    for (int nt = 0; nt < 8; nt++) {
        int col = h * 64 + nt * 8 + 2 * tg;
        float2 v0 = {oacc[nt][0] * inv0, oacc[nt][1] * inv0};
        float2 v1 = {oacc[nt][2] * inv1, oacc[nt][3] * inv1};
        *(float2*)(O + row0 * Dn + col) = v0;
        *(float2*)(O + row1 * Dn + col) = v1;
    }
}

// ---------------------------------------------------------------------------
extern "C" void kernel_launch(void* const* d_in, const int* in_sizes, int n_in,
                              void* d_out, int out_size)
{
    const float* x  = (const float*)d_in[0];
    const float* vf = (const float*)d_in[1];
    const float* wf = (const float*)d_in[2];
    float* out = (float*)d_out;

    float *v0, *v1, *v2, *q, *vv;
    __half *kh, *kx, *vth, *vtx;
    cudaGetSymbolAddress((void**)&v0,  g_v0);
    cudaGetSymbolAddress((void**)&v1,  g_v1);
    cudaGetSymbolAddress((void**)&v2,  g_v2);
    cudaGetSymbolAddress((void**)&q,   g_q);
    cudaGetSymbolAddress((void**)&vv,  g_vv);
    cudaGetSymbolAddress((void**)&kh,  g_kh);
    cudaGetSymbolAddress((void**)&kx,  g_kx);
    cudaGetSymbolAddress((void**)&vth, g_vth);
    cudaGetSymbolAddress((void**)&vtx, g_vtx);

    const size_t LL = (size_t)Ln * Ln;
    const int cblocks = (NBD / 4) / 256;

    // v0 = L0(x); {q = H0(v0), v1 = L1(v0)}; {k = H1(v1), v2 = L2(v1)}; vv = H2(v2)
    conv1_kernel<<<cblocks, 256>>>(x, v0, vf, 1);
    conv2_kernel<<<cblocks, 256>>>(v0, q, wf, 1, v1, vf + LL, 2);
    conv2s_kernel<<<cblocks, 256>>>(v1, kh, kx, wf + LL, 2, v2, vf + 2 * LL, 4);
    conv1_kernel<<<cblocks, 256>>>(v2, vv, wf + 2 * LL, 4);
    vtrans_kernel<<<dim3(Ln / 64, Bn * Hn), 256>>>(vv, vth, vtx);

    cudaFuncSetAttribute(attn_kernel,
                         cudaFuncAttributeMaxDynamicSharedMemorySize, ASMEM);
    dim3 grid(Ln / 128, Bn * Hn);   // (16, 32)
    attn_kernel<<<grid, 256, ASMEM>>>(q, kh, kx, vth, vtx, out);
}